// round 15
// baseline (speedup 1.0000x reference)
#include <cuda_runtime.h>
#include <cuda_bf16.h>
#include <cuda_fp16.h>

#define NSKU 100000
#define NWH  5000
#define NSUP 2000
#define EINTRA 400000
#define ECROSS 200000
#define TOTN (4*NSKU + NWH + NSUP)
#define SCB 98   // max 1024-blocks per type for scan

typedef unsigned long long u64;
typedef unsigned int u32;

// ------------- static scratch (no allocations allowed) -------------
__device__ __half g_Hh[6 * NSKU * 64];    // transformed sku feats per type (fp16)
__device__ float g_Ss[6 * NSKU * 4];      // src scores per type/head (fp32)
__device__ float g_SdI[4 * NSKU * 4];     // dst scores, intra types
__device__ float g_Swh[NWH * 4];
__device__ float g_Ssup[NSUP * 4];
__device__ float g_OA[NSKU * 64];
__device__ float g_OBwh[NWH * 64];
__device__ float g_OBsup[NSUP * 64];
__device__ int g_deg[TOTN];
__device__ int g_rp[4 * (NSKU + 1) + (NWH + 1) + (NSUP + 1)];
__device__ int g_col[4 * EINTRA + 2 * ECROSS];
__device__ int g_slot[4 * EINTRA + 2 * ECROSS];   // per-edge ticket from count pass
__device__ int g_bs[6 * SCB];

// ------------- tf32 helpers -------------
static __device__ __forceinline__ float to_tf32(float x) {
    u32 u; asm("cvt.rna.tf32.f32 %0, %1;" : "=r"(u) : "f"(x));
    return __uint_as_float(u);
}
static __device__ __forceinline__ void cvt4(float4& v) {
    v.x = to_tf32(v.x); v.y = to_tf32(v.y); v.z = to_tf32(v.z); v.w = to_tf32(v.w);
}
static __device__ __forceinline__ void mma_tf32(float* d, u32 a0, u32 a1, u32 a2, u32 a3,
                                                u32 b0, u32 b1) {
    asm volatile("mma.sync.aligned.m16n8k8.row.col.f32.tf32.tf32.f32 "
                 "{%0,%1,%2,%3}, {%4,%5,%6,%7}, {%8,%9}, {%0,%1,%2,%3};"
                 : "+f"(d[0]), "+f"(d[1]), "+f"(d[2]), "+f"(d[3])
                 : "r"(a0), "r"(a1), "r"(a2), "r"(a3), "r"(b0), "r"(b1));
}

struct EP6 { const int* p[6]; };
struct GP6 { const float* W[6]; const float* a[6]; };

// ------------- CSR pointer resolver -------------
static __device__ __forceinline__ void csr_ptrs(int t, int& N, int& E,
        int*& deg, int*& rp, int*& col, int*& slot) {
    if (t < 4) {
        N = NSKU; E = EINTRA;
        deg = g_deg + t * NSKU; rp = g_rp + t * (NSKU + 1);
        col = g_col + t * EINTRA; slot = g_slot + t * EINTRA;
    } else if (t == 4) {
        N = NWH; E = ECROSS;
        deg = g_deg + 4 * NSKU; rp = g_rp + 4 * (NSKU + 1);
        col = g_col + 4 * EINTRA; slot = g_slot + 4 * EINTRA;
    } else {
        N = NSUP; E = ECROSS;
        deg = g_deg + 4 * NSKU + NWH; rp = g_rp + 4 * (NSKU + 1) + (NWH + 1);
        col = g_col + 4 * EINTRA + ECROSS; slot = g_slot + 4 * EINTRA + ECROSS;
    }
}

// ------------- CSR build -------------
__global__ void zero_deg_k() {
    int i = blockIdx.x * 256 + threadIdx.x;
    if (i < TOTN) g_deg[i] = 0;
}

// 8 edges/thread; stores the atomic ticket per edge (removes atomics from fill)
__global__ void count_k(EP6 ep) {
    int t = blockIdx.y;
    int N, E; int *deg, *rp, *col, *slot;
    csr_ptrs(t, N, E, deg, rp, col, slot);
    int base = (blockIdx.x * 256 + threadIdx.x) * 8;
    if (base >= E) return;
    int4 a = *(const int4*)(ep.p[t] + E + base);
    int4 b = *(const int4*)(ep.p[t] + E + base + 4);
    int s0 = atomicAdd(&deg[a.x], 1);
    int s1 = atomicAdd(&deg[a.y], 1);
    int s2 = atomicAdd(&deg[a.z], 1);
    int s3 = atomicAdd(&deg[a.w], 1);
    int s4 = atomicAdd(&deg[b.x], 1);
    int s5 = atomicAdd(&deg[b.y], 1);
    int s6 = atomicAdd(&deg[b.z], 1);
    int s7 = atomicAdd(&deg[b.w], 1);
    *(int4*)(slot + base)     = make_int4(s0, s1, s2, s3);
    *(int4*)(slot + base + 4) = make_int4(s4, s5, s6, s7);
}

// block-local inclusive scan; rp[i] = local-exclusive; block total -> g_bs
__global__ void __launch_bounds__(1024) scanA_k() {
    int t = blockIdx.y;
    int N, E; int *deg, *rp, *col, *slot;
    csr_ptrs(t, N, E, deg, rp, col, slot);
    int nb = (N + 1023) >> 10;
    if ((int)blockIdx.x >= nb) return;
    __shared__ int wsum[32];
    int tid = threadIdx.x, lane = tid & 31, w = tid >> 5;
    int i = blockIdx.x * 1024 + tid;
    int v = (i < N) ? deg[i] : 0;
    int x = v;
    #pragma unroll
    for (int o = 1; o < 32; o <<= 1) {
        int y = __shfl_up_sync(0xffffffffu, x, o);
        if (lane >= o) x += y;
    }
    if (lane == 31) wsum[w] = x;
    __syncthreads();
    if (w == 0) {
        int s = wsum[lane];
        #pragma unroll
        for (int o = 1; o < 32; o <<= 1) {
            int y = __shfl_up_sync(0xffffffffu, s, o);
            if (lane >= o) s += y;
        }
        wsum[lane] = s;
    }
    __syncthreads();
    int incl = x + (w > 0 ? wsum[w - 1] : 0);
    if (i < N) rp[i] = incl - v;
    if (tid == 1023) g_bs[t * SCB + blockIdx.x] = incl;
}

// adds block offsets (re-scanning the tiny per-type block-sum array in smem)
// and writes rp[N]; replaces the separate scanB launch.
__global__ void __launch_bounds__(1024) scanC_k() {
    int t = blockIdx.y;
    int N, E; int *deg, *rp, *col, *slot;
    csr_ptrs(t, N, E, deg, rp, col, slot);
    int nb = (N + 1023) >> 10;
    if ((int)blockIdx.x >= nb) return;
    __shared__ int sbs[SCB];
    __shared__ int wsum[4];
    int tid = threadIdx.x, lane = tid & 31, w = tid >> 5;
    int v = (tid < nb) ? g_bs[t * SCB + tid] : 0;
    int x = v;
    #pragma unroll
    for (int o = 1; o < 32; o <<= 1) {
        int y = __shfl_up_sync(0xffffffffu, x, o);
        if (lane >= o) x += y;
    }
    if (w < 4 && lane == 31) wsum[w] = x;
    __syncthreads();
    if (tid == 0) {
        int run = 0;
        #pragma unroll
        for (int j = 0; j < 4; j++) { int s = wsum[j]; wsum[j] = run; run += s; }
    }
    __syncthreads();
    if (tid < 128) sbs[min(tid, SCB - 1)] = x + wsum[w];   // inclusive scan of block sums
    __syncthreads();
    int off = (blockIdx.x == 0) ? 0 : sbs[blockIdx.x - 1];
    int i = blockIdx.x * 1024 + tid;
    if (i < N) rp[i] += off;
    if (blockIdx.x == 0 && tid == 0) rp[N] = sbs[nb - 1];
}

// atomic-free fill: pos = rp[dst] + slot[e]; 8 edges/thread
__global__ void fill2_k(EP6 ep) {
    int t = blockIdx.y;
    int N, E; int *deg, *rp, *col, *slot;
    csr_ptrs(t, N, E, deg, rp, col, slot);
    int base = (blockIdx.x * 256 + threadIdx.x) * 8;
    if (base >= E) return;
    int4 sa = *(const int4*)(ep.p[t] + base);
    int4 sb = *(const int4*)(ep.p[t] + base + 4);
    int4 da = *(const int4*)(ep.p[t] + E + base);
    int4 db = *(const int4*)(ep.p[t] + E + base + 4);
    int4 ta = *(const int4*)(slot + base);
    int4 tb = *(const int4*)(slot + base + 4);
    col[__ldg(&rp[da.x]) + ta.x] = sa.x;
    col[__ldg(&rp[da.y]) + ta.y] = sa.y;
    col[__ldg(&rp[da.z]) + ta.z] = sa.z;
    col[__ldg(&rp[da.w]) + ta.w] = sa.w;
    col[__ldg(&rp[db.x]) + tb.x] = sb.x;
    col[__ldg(&rp[db.y]) + tb.y] = sb.y;
    col[__ldg(&rp[db.z]) + tb.z] = sb.z;
    col[__ldg(&rp[db.w]) + tb.w] = sb.w;
}

// ------------- dense phase: 2 edge-types per block, tf32 mma, fp16 H out -------------
__global__ void __launch_bounds__(256) gemm6_k(const float* __restrict__ X, GP6 gp) {
    __shared__ __align__(16) float Xs[128][36];
    __shared__ __align__(16) float WsT[2][64][36];
    int pair = blockIdx.y;                  // types 2*pair, 2*pair+1
    int tid = threadIdx.x;
    int wid = tid >> 5, lane = tid & 31;
    int g = lane >> 2, tg = lane & 3;
    int m0 = blockIdx.x * 128;
    int mw = wid * 16;

    float acc[2][8][4];
    #pragma unroll
    for (int u = 0; u < 2; u++)
        #pragma unroll
        for (int j = 0; j < 8; j++)
            #pragma unroll
            for (int c = 0; c < 4; c++) acc[u][j][c] = 0.f;

    for (int kb = 0; kb < 128; kb += 32) {
        #pragma unroll
        for (int q = 0; q < 4; q++) {
            int f = tid + q * 256;
            int row = f >> 3, c4 = (f & 7) * 4;
            int gr = m0 + row;
            float4 v = make_float4(0.f, 0.f, 0.f, 0.f);
            if (gr < NSKU) v = *(const float4*)(X + (size_t)gr * 128 + kb + c4);
            cvt4(v);
            *(float4*)&Xs[row][c4] = v;
        }
        #pragma unroll
        for (int u = 0; u < 2; u++) {
            const float* __restrict__ W = gp.W[2 * pair + u];
            #pragma unroll
            for (int q = 0; q < 2; q++) {
                int f = tid + q * 256;
                int k = f >> 4, n4 = (f & 15) * 4;
                float4 v = *(const float4*)(W + (size_t)(kb + k) * 64 + n4);
                cvt4(v);
                WsT[u][n4 + 0][k] = v.x; WsT[u][n4 + 1][k] = v.y;
                WsT[u][n4 + 2][k] = v.z; WsT[u][n4 + 3][k] = v.w;
            }
        }
        __syncthreads();
        #pragma unroll
        for (int ks = 0; ks < 4; ks++) {
            int k0 = ks * 8 + 2 * tg;
            float2 a02 = *(const float2*)&Xs[mw + g][k0];
            float2 a13 = *(const float2*)&Xs[mw + g + 8][k0];
            u32 a0 = __float_as_uint(a02.x), a1 = __float_as_uint(a13.x);
            u32 a2 = __float_as_uint(a02.y), a3 = __float_as_uint(a13.y);
            #pragma unroll
            for (int j = 0; j < 8; j++) {
                float2 b0 = *(const float2*)&WsT[0][8 * j + g][k0];
                mma_tf32(acc[0][j], a0, a1, a2, a3,
                         __float_as_uint(b0.x), __float_as_uint(b0.y));
                float2 b1 = *(const float2*)&WsT[1][8 * j + g][k0];
                mma_tf32(acc[1][j], a0, a1, a2, a3,
                         __float_as_uint(b1.x), __float_as_uint(b1.y));
            }
        }
        __syncthreads();
    }

    int r0 = m0 + mw + g;
    int r1 = r0 + 8;
    #pragma unroll
    for (int u = 0; u < 2; u++) {
        int t = 2 * pair + u;
        __half2* Hh = (__half2*)(g_Hh + (size_t)t * NSKU * 64);
        const float* av = gp.a[t];
        float* Sst = g_Ss + (size_t)t * NSKU * 4;
        float* Sdt = (t < 4) ? (g_SdI + (size_t)t * NSKU * 4) : 0;

        #pragma unroll
        for (int j = 0; j < 8; j++) {
            int c2 = 4 * j + tg;   // half2 index within row
            if (r0 < NSKU) Hh[(size_t)r0 * 32 + c2] = __floats2half2_rn(acc[u][j][0], acc[u][j][1]);
            if (r1 < NSKU) Hh[(size_t)r1 * 32 + c2] = __floats2half2_rn(acc[u][j][2], acc[u][j][3]);
        }

        float2 sA0 = *(const float2*)(av + 2 * tg);
        float2 sA1 = *(const float2*)(av + 8 + 2 * tg);
        float2 dA0 = *(const float2*)(av + 16 + 2 * tg);
        float2 dA1 = *(const float2*)(av + 24 + 2 * tg);
        #pragma unroll
        for (int h = 0; h < 4; h++) {
            float p0 = acc[u][2*h][0] * sA0.x + acc[u][2*h][1] * sA0.y
                     + acc[u][2*h+1][0] * sA1.x + acc[u][2*h+1][1] * sA1.y;
            float p1 = acc[u][2*h][2] * sA0.x + acc[u][2*h][3] * sA0.y
                     + acc[u][2*h+1][2] * sA1.x + acc[u][2*h+1][3] * sA1.y;
            float q0 = acc[u][2*h][0] * dA0.x + acc[u][2*h][1] * dA0.y
                     + acc[u][2*h+1][0] * dA1.x + acc[u][2*h+1][1] * dA1.y;
            float q1 = acc[u][2*h][2] * dA0.x + acc[u][2*h][3] * dA0.y
                     + acc[u][2*h+1][2] * dA1.x + acc[u][2*h+1][3] * dA1.y;
            #pragma unroll
            for (int o = 1; o < 4; o <<= 1) {
                p0 += __shfl_xor_sync(0xffffffffu, p0, o);
                p1 += __shfl_xor_sync(0xffffffffu, p1, o);
                q0 += __shfl_xor_sync(0xffffffffu, q0, o);
                q1 += __shfl_xor_sync(0xffffffffu, q1, o);
            }
            if (tg == 0) {
                if (r0 < NSKU) { Sst[r0 * 4 + h] = p0; if (Sdt) Sdt[r0 * 4 + h] = q0; }
                if (r1 < NSKU) { Sst[r1 * 4 + h] = p1; if (Sdt) Sdt[r1 * 4 + h] = q1; }
            }
        }
    }
}

// ------------- dst-side scores for BOTH cross types in one launch -------------
__global__ void dstscore2_k(const float* __restrict__ Xwh, const float* __restrict__ Xsup,
                            const float* __restrict__ Wwh, const float* __restrict__ Wsup,
                            const float* __restrict__ awh, const float* __restrict__ asup) {
    int n = blockIdx.x;
    const float* X; const float* W; const float* av; float* S;
    if (n < NWH) { X = Xwh; W = Wwh; av = awh; S = g_Swh; }
    else         { n -= NWH; X = Xsup; W = Wsup; av = asup; S = g_Ssup; }
    int d = threadIdx.x;
    const float* xr = X + (size_t)n * 128;
    float h = 0.f;
    for (int k = 0; k < 128; k++) h += xr[k] * W[k * 64 + d];
    float p = h * av[16 + (d & 15)];
    #pragma unroll
    for (int o = 1; o < 16; o <<= 1) p += __shfl_xor_sync(0xffffffffu, p, o);
    if ((d & 15) == 0) S[n * 4 + (d >> 4)] = p;
}

// ------------- edge weight helper -------------
static __device__ __forceinline__ float edge_w(float x) {
    float el = x > 0.f ? x : (__expf(x) - 1.f);
    return __expf(el);
}

// ------------- edge aggregation: one warp per dst, serial types, unroll-4 -------
__global__ void agg_intra_k() {
    int warp = (blockIdx.x * blockDim.x + threadIdx.x) >> 5;
    int lane = threadIdx.x & 31;
    if (warp >= NSKU) return;
    int dst = warp;
    int head = lane >> 3;
    float2 tot = make_float2(0.f, 0.f);
    #pragma unroll
    for (int t = 0; t < 4; t++) {
        const int* rp = g_rp + t * (NSKU + 1);
        const int* col = g_col + t * EINTRA;
        const float* Ss = g_Ss + (size_t)t * NSKU * 4;
        const float* Sd = g_SdI + (size_t)t * NSKU * 4;
        const __half2* Hh = (const __half2*)(g_Hh + (size_t)t * NSKU * 64);
        float sd = Sd[dst * 4 + head];
        float2 acc = make_float2(0.f, 0.f);
        float den = 0.f;
        int e = rp[dst], e1 = rp[dst + 1];
        for (; e + 3 < e1; e += 4) {
            int s0 = __ldg(&col[e]);
            int s1 = __ldg(&col[e + 1]);
            int s2 = __ldg(&col[e + 2]);
            int s3 = __ldg(&col[e + 3]);
            float x0 = __ldg(&Ss[s0 * 4 + head]) + sd;
            float x1 = __ldg(&Ss[s1 * 4 + head]) + sd;
            float x2 = __ldg(&Ss[s2 * 4 + head]) + sd;
            float x3 = __ldg(&Ss[s3 * 4 + head]) + sd;
            float2 h0 = __half22float2(Hh[(size_t)s0 * 32 + lane]);
            float2 h1 = __half22float2(Hh[(size_t)s1 * 32 + lane]);
            float2 h2 = __half22float2(Hh[(size_t)s2 * 32 + lane]);
            float2 h3 = __half22float2(Hh[(size_t)s3 * 32 + lane]);
            float w0 = edge_w(x0), w1 = edge_w(x1), w2 = edge_w(x2), w3 = edge_w(x3);
            acc.x += w0 * h0.x + w1 * h1.x + w2 * h2.x + w3 * h3.x;
            acc.y += w0 * h0.y + w1 * h1.y + w2 * h2.y + w3 * h3.y;
            den += w0 + w1 + w2 + w3;
        }
        for (; e < e1; e++) {
            int s0 = __ldg(&col[e]);
            float x0 = __ldg(&Ss[s0 * 4 + head]) + sd;
            float2 h0 = __half22float2(Hh[(size_t)s0 * 32 + lane]);
            float w0 = edge_w(x0);
            acc.x += w0 * h0.x; acc.y += w0 * h0.y; den += w0;
        }
        float inv = 1.f / (den + 1e-12f);
        tot.x += acc.x * inv; tot.y += acc.y * inv;
    }
    *(float2*)(g_OA + (size_t)dst * 64 + 2 * lane) = tot;
}

// both cross types in one launch: warps [0,NWH) -> type 4, [NWH,NWH+NSUP) -> type 5
__global__ void agg_crossM_k() {
    int warp = (blockIdx.x * blockDim.x + threadIdx.x) >> 5;
    int lane = threadIdx.x & 31;
    if (warp >= NWH + NSUP) return;
    int t, dst;
    if (warp < NWH) { t = 4; dst = warp; }
    else            { t = 5; dst = warp - NWH; }
    int head = lane >> 3;
    const int* rp = g_rp + 4 * (NSKU + 1) + (t == 5 ? (NWH + 1) : 0);
    const int* col = g_col + 4 * EINTRA + (t == 5 ? ECROSS : 0);
    const float* Ss = g_Ss + (size_t)t * NSKU * 4;
    const float* Sd = (t == 4) ? g_Swh : g_Ssup;
    const __half2* Hh = (const __half2*)(g_Hh + (size_t)t * NSKU * 64);
    float* Out = (t == 4) ? g_OBwh : g_OBsup;
    float sd = Sd[dst * 4 + head];
    float2 acc = make_float2(0.f, 0.f);
    float den = 0.f;
    int e = rp[dst], e1 = rp[dst + 1];
    for (; e + 3 < e1; e += 4) {
        int s0 = __ldg(&col[e]);
        int s1 = __ldg(&col[e + 1]);
        int s2 = __ldg(&col[e + 2]);
        int s3 = __ldg(&col[e + 3]);
        float x0 = __ldg(&Ss[s0 * 4 + head]) + sd;
        float x1 = __ldg(&Ss[s1 * 4 + head]) + sd;
        float x2 = __ldg(&Ss[s2 * 4 + head]) + sd;
        float x3 = __ldg(&Ss[s3 * 4 + head]) + sd;
        float2 h0 = __half22float2(Hh[(size_t)s0 * 32 + lane]);
        float2 h1 = __half22float2(Hh[(size_t)s1 * 32 + lane]);
        float2 h2 = __half22float2(Hh[(size_t)s2 * 32 + lane]);
        float2 h3 = __half22float2(Hh[(size_t)s3 * 32 + lane]);
        float w0 = edge_w(x0), w1 = edge_w(x1), w2 = edge_w(x2), w3 = edge_w(x3);
        acc.x += w0 * h0.x + w1 * h1.x + w2 * h2.x + w3 * h3.x;
        acc.y += w0 * h0.y + w1 * h1.y + w2 * h2.y + w3 * h3.y;
        den += w0 + w1 + w2 + w3;
    }
    for (; e < e1; e++) {
        int s0 = __ldg(&col[e]);
        float x0 = __ldg(&Ss[s0 * 4 + head]) + sd;
        float2 h0 = __half22float2(Hh[(size_t)s0 * 32 + lane]);
        float w0 = edge_w(x0);
        acc.x += w0 * h0.x; acc.y += w0 * h0.y; den += w0;
    }
    float inv = 1.f / (den + 1e-12f);
    *(float2*)(Out + (size_t)dst * 64 + 2 * lane) = make_float2(acc.x * inv, acc.y * inv);
}

// ------------- finish: tf32 mma GEMM [G|X] @ [PW;RW], fused LayerNorm -------------
__global__ void __launch_bounds__(256) finishT_k(
        const float* __restrict__ X, const float* __restrict__ PW,
        const float* __restrict__ RW, const float* __restrict__ pb,
        const float* __restrict__ lg, const float* __restrict__ lb,
        float* __restrict__ out, int N, int which) {
    const float* __restrict__ G = (which == 0) ? g_OA : (which == 1) ? g_OBwh : g_OBsup;
    __shared__ __align__(16) float As[128][36];
    __shared__ __align__(16) float BsT[64][36];
    int tid = threadIdx.x;
    int wid = tid >> 5, lane = tid & 31;
    int g = lane >> 2, tg = lane & 3;
    int m0 = blockIdx.x * 128;
    int mw = wid * 16;

    float acc[8][4];
    #pragma unroll
    for (int j = 0; j < 8; j++)
        #pragma unroll
        for (int c = 0; c < 4; c++) acc[j][c] = 0.f;

    for (int kb = 0; kb < 192; kb += 32) {
        #pragma unroll
        for (int q = 0; q < 4; q++) {
            int f = tid + q * 256;
            int row = f >> 3, c4 = (f & 7) * 4;
            int gr = m0 + row;
            int k = kb + c4;
            float4 v = make_float4(0.f, 0.f, 0.f, 0.f);
            if (gr < N) {
                if (k < 64) v = *(const float4*)(G + (size_t)gr * 64 + k);
                else        v = *(const float4*)(X + (size_t)gr * 128 + (k - 64));
            }
            cvt4(v);
            *(float4*)&As[row][c4] = v;
        }
        #pragma unroll
        for (int q = 0; q < 2; q++) {
            int f = tid + q * 256;
            int k = f >> 4, n4 = (f & 15) * 4;
            int gk = kb + k;
            const float* src = (gk < 64) ? (PW + (size_t)gk * 64)
                                         : (RW + (size_t)(gk - 64) * 64);
            float4 v = *(const float4*)(src + n4);
            cvt4(v);
            BsT[n4 + 0][k] = v.x; BsT[n4 + 1][k] = v.y;
            BsT[n4 + 2][k] = v.z; BsT[n4 + 3][k] = v.w;
        }
        __syncthreads();
        #pragma unroll
        for (int ks = 0; ks < 4; ks++) {
            int k0 = ks * 8 + 2 * tg;
            float2 a02 = *(const float2*)&As[mw + g][k0];
            float2 a13 = *(const float2*)&As[mw + g + 8][k0];
            u32 a0 = __float_as_uint(a02.x), a1 = __float_as_uint(a13.x);
            u32 a2 = __float_as_uint(a02.y), a3 = __float_as_uint(a13.y);
            #pragma unroll
            for (int j = 0; j < 8; j++) {
                float2 b01 = *(const float2*)&BsT[8 * j + g][k0];
                mma_tf32(acc[j], a0, a1, a2, a3,
                         __float_as_uint(b01.x), __float_as_uint(b01.y));
            }
        }
        __syncthreads();
    }

    int r0 = m0 + mw + g;
    int r1 = r0 + 8;
    float y0[8][2], y1[8][2];
    float s1a = 0.f, s2a = 0.f, s1b = 0.f, s2b = 0.f;
    #pragma unroll
    for (int j = 0; j < 8; j++) {
        float2 pbv = *(const float2*)(pb + 8 * j + 2 * tg);
        y0[j][0] = acc[j][0] + pbv.x; y0[j][1] = acc[j][1] + pbv.y;
        y1[j][0] = acc[j][2] + pbv.x; y1[j][1] = acc[j][3] + pbv.y;
        s1a += y0[j][0] + y0[j][1];
        s2a += y0[j][0] * y0[j][0] + y0[j][1] * y0[j][1];
        s1b += y1[j][0] + y1[j][1];
        s2b += y1[j][0] * y1[j][0] + y1[j][1] * y1[j][1];
    }
    #pragma unroll
    for (int o = 1; o < 4; o <<= 1) {
        s1a += __shfl_xor_sync(0xffffffffu, s1a, o);
        s2a += __shfl_xor_sync(0xffffffffu, s2a, o);
        s1b += __shfl_xor_sync(0xffffffffu, s1b, o);
        s2b += __shfl_xor_sync(0xffffffffu, s2b, o);
    }
    float mua = s1a * (1.f / 64.f);
    float vara = s2a * (1.f / 64.f) - mua * mua;
    float inva = rsqrtf(vara + 1e-5f);
    float mub = s1b * (1.f / 64.f);
    float varb = s2b * (1.f / 64.f) - mub * mub;
    float invb = rsqrtf(varb + 1e-5f);
    #pragma unroll
    for (int j = 0; j < 8; j++) {
        int c = 8 * j + 2 * tg;
        float2 gv = *(const float2*)(lg + c);
        float2 bv = *(const float2*)(lb + c);
        if (r0 < N)
            *(float2*)(out + (size_t)r0 * 64 + c) =
                make_float2((y0[j][0] - mua) * inva * gv.x + bv.x,
                            (y0[j][1] - mua) * inva * gv.y + bv.y);
        if (r1 < N)
            *(float2*)(out + (size_t)r1 * 64 + c) =
                make_float2((y1[j][0] - mub) * invb * gv.x + bv.x,
                            (y1[j][1] - mub) * invb * gv.y + bv.y);
    }
}

// ------------- launch (3-stream DAG) -------------
extern "C" void kernel_launch(void* const* d_in, const int* in_sizes, int n_in,
                              void* d_out, int out_size) {
    const float* x_sku = (const float*)d_in[0];
    const float* x_wh  = (const float*)d_in[1];
    const float* x_sup = (const float*)d_in[2];
    GP6 gp; EP6 ep;
    for (int i = 0; i < 6; i++) {
        gp.W[i] = (const float*)d_in[3 + 2 * i];
        gp.a[i] = (const float*)d_in[4 + 2 * i];
    }
    const float* proj_W = (const float*)d_in[15];
    const float* proj_b = (const float*)d_in[16];
    const float* ln_g   = (const float*)d_in[17];
    const float* ln_b   = (const float*)d_in[18];
    const float* res_W  = (const float*)d_in[19];
    for (int i = 0; i < 6; i++) ep.p[i] = (const int*)d_in[20 + i];
    float* out = (float*)d_out;

    static cudaStream_t s1 = 0, s2 = 0;
    static cudaEvent_t ev_root = 0, ev_csr = 0, ev_gemm = 0, ev_s2 = 0;
    if (!s1) {
        cudaStreamCreateWithFlags(&s1, cudaStreamNonBlocking);
        cudaStreamCreateWithFlags(&s2, cudaStreamNonBlocking);
        cudaEventCreateWithFlags(&ev_root, cudaEventDisableTiming);
        cudaEventCreateWithFlags(&ev_csr, cudaEventDisableTiming);
        cudaEventCreateWithFlags(&ev_gemm, cudaEventDisableTiming);
        cudaEventCreateWithFlags(&ev_s2, cudaEventDisableTiming);
    }

    // fork
    cudaEventRecord(ev_root, 0);
    cudaStreamWaitEvent(s1, ev_root, 0);
    cudaStreamWaitEvent(s2, ev_root, 0);

    // S1: CSR build (ticketed count -> scanA -> scanC(+blocksum) -> atomic-free fill)
    zero_deg_k<<<(TOTN + 255) / 256, 256, 0, s1>>>();
    count_k<<<dim3((EINTRA / 8 + 255) / 256, 6), 256, 0, s1>>>(ep);
    scanA_k<<<dim3(SCB, 6), 1024, 0, s1>>>();
    scanC_k<<<dim3(SCB, 6), 1024, 0, s1>>>();
    fill2_k<<<dim3((EINTRA / 8 + 255) / 256, 6), 256, 0, s1>>>(ep);
    cudaEventRecord(ev_csr, s1);

    // S2: dst-side scores (merged wh+sup)
    dstscore2_k<<<NWH + NSUP, 64, 0, s2>>>(x_wh, x_sup, gp.W[4], gp.W[5],
                                           gp.a[4], gp.a[5]);

    // S0: dense phase (tf32 tensor cores, 2 types per block, all 3 pairs)
    gemm6_k<<<dim3((NSKU + 127) / 128, 3), 256>>>(x_sku, gp);
    cudaEventRecord(ev_gemm, 0);

    // S0: sku chain
    cudaStreamWaitEvent(0, ev_csr, 0);
    agg_intra_k<<<(NSKU * 32 + 255) / 256, 256>>>();
    finishT_k<<<(NSKU + 127) / 128, 256>>>(x_sku, proj_W, res_W, proj_b, ln_g, ln_b,
                                           out, NSKU, 0);

    // S2: cross chains (merged agg)
    cudaStreamWaitEvent(s2, ev_gemm, 0);
    cudaStreamWaitEvent(s2, ev_csr, 0);
    agg_crossM_k<<<((NWH + NSUP) * 32 + 255) / 256, 256, 0, s2>>>();
    finishT_k<<<(NWH + 127) / 128, 256, 0, s2>>>(x_wh, proj_W + 64 * 64, res_W, proj_b,
                                                 ln_g, ln_b, out + (size_t)NSKU * 64, NWH, 1);
    finishT_k<<<(NSUP + 127) / 128, 256, 0, s2>>>(x_sup, proj_W + 64 * 64, res_W, proj_b,
                                                  ln_g, ln_b, out + (size_t)(NSKU + NWH) * 64,
                                                  NSUP, 2);
    cudaEventRecord(ev_s2, s2);

    // join
    cudaStreamWaitEvent(0, ev_s2, 0);
}

// round 17
// speedup vs baseline: 1.5174x; 1.5174x over previous
#include <cuda_runtime.h>
#include <cuda_bf16.h>
#include <cuda_fp16.h>

#define NSKU 100000
#define NWH  5000
#define NSUP 2000
#define EINTRA 400000
#define ECROSS 200000
#define TOTN (4*NSKU + NWH + NSUP)
#define SCB 98   // max 1024-blocks per type for scan

typedef unsigned long long u64;
typedef unsigned int u32;

// ------------- static scratch (no allocations allowed) -------------
__device__ __half g_Hh[6 * NSKU * 64];    // transformed sku feats per type (fp16)
__device__ float g_Ss[6 * NSKU * 4];      // src scores per type/head (fp32)
__device__ float g_SdI[4 * NSKU * 4];     // dst scores, intra types
__device__ float g_Swh[NWH * 4];
__device__ float g_Ssup[NSUP * 4];
__device__ float g_OA[NSKU * 64];
__device__ float g_OBwh[NWH * 64];
__device__ float g_OBsup[NSUP * 64];
__device__ int g_deg[TOTN];
__device__ int g_rp[4 * (NSKU + 1) + (NWH + 1) + (NSUP + 1)];
__device__ int g_col[4 * EINTRA + 2 * ECROSS];
__device__ int g_slot[4 * EINTRA + 2 * ECROSS];   // per-edge ticket from count pass
__device__ int g_bs[6 * SCB];

// ------------- tf32 helpers -------------
static __device__ __forceinline__ float to_tf32(float x) {
    u32 u; asm("cvt.rna.tf32.f32 %0, %1;" : "=r"(u) : "f"(x));
    return __uint_as_float(u);
}
static __device__ __forceinline__ void cvt4(float4& v) {
    v.x = to_tf32(v.x); v.y = to_tf32(v.y); v.z = to_tf32(v.z); v.w = to_tf32(v.w);
}
static __device__ __forceinline__ void mma_tf32(float* d, u32 a0, u32 a1, u32 a2, u32 a3,
                                                u32 b0, u32 b1) {
    asm volatile("mma.sync.aligned.m16n8k8.row.col.f32.tf32.tf32.f32 "
                 "{%0,%1,%2,%3}, {%4,%5,%6,%7}, {%8,%9}, {%0,%1,%2,%3};"
                 : "+f"(d[0]), "+f"(d[1]), "+f"(d[2]), "+f"(d[3])
                 : "r"(a0), "r"(a1), "r"(a2), "r"(a3), "r"(b0), "r"(b1));
}

struct EP6 { const int* p[6]; };
struct GP6 { const float* W[6]; const float* a[6]; };

// ------------- CSR pointer resolver -------------
static __device__ __forceinline__ void csr_ptrs(int t, int& N, int& E,
        int*& deg, int*& rp, int*& col, int*& slot) {
    if (t < 4) {
        N = NSKU; E = EINTRA;
        deg = g_deg + t * NSKU; rp = g_rp + t * (NSKU + 1);
        col = g_col + t * EINTRA; slot = g_slot + t * EINTRA;
    } else if (t == 4) {
        N = NWH; E = ECROSS;
        deg = g_deg + 4 * NSKU; rp = g_rp + 4 * (NSKU + 1);
        col = g_col + 4 * EINTRA; slot = g_slot + 4 * EINTRA;
    } else {
        N = NSUP; E = ECROSS;
        deg = g_deg + 4 * NSKU + NWH; rp = g_rp + 4 * (NSKU + 1) + (NWH + 1);
        col = g_col + 4 * EINTRA + ECROSS; slot = g_slot + 4 * EINTRA + ECROSS;
    }
}

// ------------- CSR build -------------
__global__ void zero_deg_k() {
    int i = blockIdx.x * 256 + threadIdx.x;
    if (i < TOTN) g_deg[i] = 0;
}

// 8 edges/thread; stores the atomic ticket per edge (removes atomics from fill)
__global__ void count_k(EP6 ep) {
    int t = blockIdx.y;
    int N, E; int *deg, *rp, *col, *slot;
    csr_ptrs(t, N, E, deg, rp, col, slot);
    int base = (blockIdx.x * 256 + threadIdx.x) * 8;
    if (base >= E) return;
    int4 a = *(const int4*)(ep.p[t] + E + base);
    int4 b = *(const int4*)(ep.p[t] + E + base + 4);
    int s0 = atomicAdd(&deg[a.x], 1);
    int s1 = atomicAdd(&deg[a.y], 1);
    int s2 = atomicAdd(&deg[a.z], 1);
    int s3 = atomicAdd(&deg[a.w], 1);
    int s4 = atomicAdd(&deg[b.x], 1);
    int s5 = atomicAdd(&deg[b.y], 1);
    int s6 = atomicAdd(&deg[b.z], 1);
    int s7 = atomicAdd(&deg[b.w], 1);
    *(int4*)(slot + base)     = make_int4(s0, s1, s2, s3);
    *(int4*)(slot + base + 4) = make_int4(s4, s5, s6, s7);
}

// block-local inclusive scan; rp[i] = local-exclusive; block total -> g_bs
__global__ void __launch_bounds__(1024) scanA_k() {
    int t = blockIdx.y;
    int N, E; int *deg, *rp, *col, *slot;
    csr_ptrs(t, N, E, deg, rp, col, slot);
    int nb = (N + 1023) >> 10;
    if ((int)blockIdx.x >= nb) return;
    __shared__ int wsum[32];
    int tid = threadIdx.x, lane = tid & 31, w = tid >> 5;
    int i = blockIdx.x * 1024 + tid;
    int v = (i < N) ? deg[i] : 0;
    int x = v;
    #pragma unroll
    for (int o = 1; o < 32; o <<= 1) {
        int y = __shfl_up_sync(0xffffffffu, x, o);
        if (lane >= o) x += y;
    }
    if (lane == 31) wsum[w] = x;
    __syncthreads();
    if (w == 0) {
        int s = wsum[lane];
        #pragma unroll
        for (int o = 1; o < 32; o <<= 1) {
            int y = __shfl_up_sync(0xffffffffu, s, o);
            if (lane >= o) s += y;
        }
        wsum[lane] = s;
    }
    __syncthreads();
    int incl = x + (w > 0 ? wsum[w - 1] : 0);
    if (i < N) rp[i] = incl - v;
    if (tid == 1023) g_bs[t * SCB + blockIdx.x] = incl;
}

// adds block offsets (re-scanning the tiny per-type block-sum array in smem)
// and writes rp[N]; replaces the separate scanB launch.
__global__ void __launch_bounds__(1024) scanC_k() {
    int t = blockIdx.y;
    int N, E; int *deg, *rp, *col, *slot;
    csr_ptrs(t, N, E, deg, rp, col, slot);
    int nb = (N + 1023) >> 10;
    if ((int)blockIdx.x >= nb) return;
    __shared__ int sbs[SCB];
    __shared__ int wsum[4];
    int tid = threadIdx.x, lane = tid & 31, w = tid >> 5;
    int v = (tid < nb) ? g_bs[t * SCB + tid] : 0;
    int x = v;
    #pragma unroll
    for (int o = 1; o < 32; o <<= 1) {
        int y = __shfl_up_sync(0xffffffffu, x, o);
        if (lane >= o) x += y;
    }
    if (w < 4 && lane == 31) wsum[w] = x;
    __syncthreads();
    if (tid == 0) {
        int run = 0;
        #pragma unroll
        for (int j = 0; j < 4; j++) { int s = wsum[j]; wsum[j] = run; run += s; }
    }
    __syncthreads();
    if (tid < 128) sbs[min(tid, SCB - 1)] = x + wsum[w];   // inclusive scan of block sums
    __syncthreads();
    int off = (blockIdx.x == 0) ? 0 : sbs[blockIdx.x - 1];
    int i = blockIdx.x * 1024 + tid;
    if (i < N) rp[i] += off;
    if (blockIdx.x == 0 && tid == 0) rp[N] = sbs[nb - 1];
}

// atomic-free fill: pos = rp[dst] + slot[e]; 8 edges/thread
__global__ void fill2_k(EP6 ep) {
    int t = blockIdx.y;
    int N, E; int *deg, *rp, *col, *slot;
    csr_ptrs(t, N, E, deg, rp, col, slot);
    int base = (blockIdx.x * 256 + threadIdx.x) * 8;
    if (base >= E) return;
    int4 sa = *(const int4*)(ep.p[t] + base);
    int4 sb = *(const int4*)(ep.p[t] + base + 4);
    int4 da = *(const int4*)(ep.p[t] + E + base);
    int4 db = *(const int4*)(ep.p[t] + E + base + 4);
    int4 ta = *(const int4*)(slot + base);
    int4 tb = *(const int4*)(slot + base + 4);
    col[__ldg(&rp[da.x]) + ta.x] = sa.x;
    col[__ldg(&rp[da.y]) + ta.y] = sa.y;
    col[__ldg(&rp[da.z]) + ta.z] = sa.z;
    col[__ldg(&rp[da.w]) + ta.w] = sa.w;
    col[__ldg(&rp[db.x]) + tb.x] = sb.x;
    col[__ldg(&rp[db.y]) + tb.y] = sb.y;
    col[__ldg(&rp[db.z]) + tb.z] = sb.z;
    col[__ldg(&rp[db.w]) + tb.w] = sb.w;
}

// ------------- dense phase: 2 edge-types per block, tf32 mma, fp16 H out -------------
__global__ void __launch_bounds__(256) gemm6_k(const float* __restrict__ X, GP6 gp) {
    __shared__ __align__(16) float Xs[128][36];
    __shared__ __align__(16) float WsT[2][64][36];
    int pair = blockIdx.y;                  // types 2*pair, 2*pair+1
    int tid = threadIdx.x;
    int wid = tid >> 5, lane = tid & 31;
    int g = lane >> 2, tg = lane & 3;
    int m0 = blockIdx.x * 128;
    int mw = wid * 16;

    float acc[2][8][4];
    #pragma unroll
    for (int u = 0; u < 2; u++)
        #pragma unroll
        for (int j = 0; j < 8; j++)
            #pragma unroll
            for (int c = 0; c < 4; c++) acc[u][j][c] = 0.f;

    for (int kb = 0; kb < 128; kb += 32) {
        #pragma unroll
        for (int q = 0; q < 4; q++) {
            int f = tid + q * 256;
            int row = f >> 3, c4 = (f & 7) * 4;
            int gr = m0 + row;
            float4 v = make_float4(0.f, 0.f, 0.f, 0.f);
            if (gr < NSKU) v = *(const float4*)(X + (size_t)gr * 128 + kb + c4);
            cvt4(v);
            *(float4*)&Xs[row][c4] = v;
        }
        #pragma unroll
        for (int u = 0; u < 2; u++) {
            const float* __restrict__ W = gp.W[2 * pair + u];
            #pragma unroll
            for (int q = 0; q < 2; q++) {
                int f = tid + q * 256;
                int k = f >> 4, n4 = (f & 15) * 4;
                float4 v = *(const float4*)(W + (size_t)(kb + k) * 64 + n4);
                cvt4(v);
                WsT[u][n4 + 0][k] = v.x; WsT[u][n4 + 1][k] = v.y;
                WsT[u][n4 + 2][k] = v.z; WsT[u][n4 + 3][k] = v.w;
            }
        }
        __syncthreads();
        #pragma unroll
        for (int ks = 0; ks < 4; ks++) {
            int k0 = ks * 8 + 2 * tg;
            float2 a02 = *(const float2*)&Xs[mw + g][k0];
            float2 a13 = *(const float2*)&Xs[mw + g + 8][k0];
            u32 a0 = __float_as_uint(a02.x), a1 = __float_as_uint(a13.x);
            u32 a2 = __float_as_uint(a02.y), a3 = __float_as_uint(a13.y);
            #pragma unroll
            for (int j = 0; j < 8; j++) {
                float2 b0 = *(const float2*)&WsT[0][8 * j + g][k0];
                mma_tf32(acc[0][j], a0, a1, a2, a3,
                         __float_as_uint(b0.x), __float_as_uint(b0.y));
                float2 b1 = *(const float2*)&WsT[1][8 * j + g][k0];
                mma_tf32(acc[1][j], a0, a1, a2, a3,
                         __float_as_uint(b1.x), __float_as_uint(b1.y));
            }
        }
        __syncthreads();
    }

    int r0 = m0 + mw + g;
    int r1 = r0 + 8;
    #pragma unroll
    for (int u = 0; u < 2; u++) {
        int t = 2 * pair + u;
        __half2* Hh = (__half2*)(g_Hh + (size_t)t * NSKU * 64);
        const float* av = gp.a[t];
        float* Sst = g_Ss + (size_t)t * NSKU * 4;
        float* Sdt = (t < 4) ? (g_SdI + (size_t)t * NSKU * 4) : 0;

        #pragma unroll
        for (int j = 0; j < 8; j++) {
            int c2 = 4 * j + tg;   // half2 index within row
            if (r0 < NSKU) Hh[(size_t)r0 * 32 + c2] = __floats2half2_rn(acc[u][j][0], acc[u][j][1]);
            if (r1 < NSKU) Hh[(size_t)r1 * 32 + c2] = __floats2half2_rn(acc[u][j][2], acc[u][j][3]);
        }

        float2 sA0 = *(const float2*)(av + 2 * tg);
        float2 sA1 = *(const float2*)(av + 8 + 2 * tg);
        float2 dA0 = *(const float2*)(av + 16 + 2 * tg);
        float2 dA1 = *(const float2*)(av + 24 + 2 * tg);
        #pragma unroll
        for (int h = 0; h < 4; h++) {
            float p0 = acc[u][2*h][0] * sA0.x + acc[u][2*h][1] * sA0.y
                     + acc[u][2*h+1][0] * sA1.x + acc[u][2*h+1][1] * sA1.y;
            float p1 = acc[u][2*h][2] * sA0.x + acc[u][2*h][3] * sA0.y
                     + acc[u][2*h+1][2] * sA1.x + acc[u][2*h+1][3] * sA1.y;
            float q0 = acc[u][2*h][0] * dA0.x + acc[u][2*h][1] * dA0.y
                     + acc[u][2*h+1][0] * dA1.x + acc[u][2*h+1][1] * dA1.y;
            float q1 = acc[u][2*h][2] * dA0.x + acc[u][2*h][3] * dA0.y
                     + acc[u][2*h+1][2] * dA1.x + acc[u][2*h+1][3] * dA1.y;
            #pragma unroll
            for (int o = 1; o < 4; o <<= 1) {
                p0 += __shfl_xor_sync(0xffffffffu, p0, o);
                p1 += __shfl_xor_sync(0xffffffffu, p1, o);
                q0 += __shfl_xor_sync(0xffffffffu, q0, o);
                q1 += __shfl_xor_sync(0xffffffffu, q1, o);
            }
            if (tg == 0) {
                if (r0 < NSKU) { Sst[r0 * 4 + h] = p0; if (Sdt) Sdt[r0 * 4 + h] = q0; }
                if (r1 < NSKU) { Sst[r1 * 4 + h] = p1; if (Sdt) Sdt[r1 * 4 + h] = q1; }
            }
        }
    }
}

// ------------- dst-side scores for BOTH cross types in one launch -------------
__global__ void dstscore2_k(const float* __restrict__ Xwh, const float* __restrict__ Xsup,
                            const float* __restrict__ Wwh, const float* __restrict__ Wsup,
                            const float* __restrict__ awh, const float* __restrict__ asup) {
    int n = blockIdx.x;
    const float* X; const float* W; const float* av; float* S;
    if (n < NWH) { X = Xwh; W = Wwh; av = awh; S = g_Swh; }
    else         { n -= NWH; X = Xsup; W = Wsup; av = asup; S = g_Ssup; }
    int d = threadIdx.x;
    const float* xr = X + (size_t)n * 128;
    float h = 0.f;
    for (int k = 0; k < 128; k++) h += xr[k] * W[k * 64 + d];
    float p = h * av[16 + (d & 15)];
    #pragma unroll
    for (int o = 1; o < 16; o <<= 1) p += __shfl_xor_sync(0xffffffffu, p, o);
    if ((d & 15) == 0) S[n * 4 + (d >> 4)] = p;
}

// ------------- edge aggregation: one warp per dst, serial types, unroll-2 -------
__global__ void agg_intra_k() {
    int warp = (blockIdx.x * blockDim.x + threadIdx.x) >> 5;
    int lane = threadIdx.x & 31;
    if (warp >= NSKU) return;
    int dst = warp;
    int head = lane >> 3;
    float2 tot = make_float2(0.f, 0.f);
    #pragma unroll
    for (int t = 0; t < 4; t++) {
        const int* rp = g_rp + t * (NSKU + 1);
        const int* col = g_col + t * EINTRA;
        const float* Ss = g_Ss + (size_t)t * NSKU * 4;
        const float* Sd = g_SdI + (size_t)t * NSKU * 4;
        const __half2* Hh = (const __half2*)(g_Hh + (size_t)t * NSKU * 64);
        float sd = Sd[dst * 4 + head];
        float2 acc = make_float2(0.f, 0.f);
        float den = 0.f;
        int e = rp[dst], e1 = rp[dst + 1];
        for (; e + 1 < e1; e += 2) {
            int s0 = __ldg(&col[e]);
            int s1 = __ldg(&col[e + 1]);
            float x0 = __ldg(&Ss[s0 * 4 + head]) + sd;
            float x1 = __ldg(&Ss[s1 * 4 + head]) + sd;
            float2 h0 = __half22float2(Hh[(size_t)s0 * 32 + lane]);
            float2 h1 = __half22float2(Hh[(size_t)s1 * 32 + lane]);
            float el0 = x0 > 0.f ? x0 : (__expf(x0) - 1.f);
            float el1 = x1 > 0.f ? x1 : (__expf(x1) - 1.f);
            float w0 = __expf(el0), w1 = __expf(el1);
            acc.x += w0 * h0.x + w1 * h1.x;
            acc.y += w0 * h0.y + w1 * h1.y;
            den += w0 + w1;
        }
        if (e < e1) {
            int s0 = __ldg(&col[e]);
            float x0 = __ldg(&Ss[s0 * 4 + head]) + sd;
            float2 h0 = __half22float2(Hh[(size_t)s0 * 32 + lane]);
            float el0 = x0 > 0.f ? x0 : (__expf(x0) - 1.f);
            float w0 = __expf(el0);
            acc.x += w0 * h0.x; acc.y += w0 * h0.y; den += w0;
        }
        float inv = 1.f / (den + 1e-12f);
        tot.x += acc.x * inv; tot.y += acc.y * inv;
    }
    *(float2*)(g_OA + (size_t)dst * 64 + 2 * lane) = tot;
}

// both cross types in one launch: warps [0,NWH) -> type 4, [NWH,NWH+NSUP) -> type 5
__global__ void agg_crossM_k() {
    int warp = (blockIdx.x * blockDim.x + threadIdx.x) >> 5;
    int lane = threadIdx.x & 31;
    if (warp >= NWH + NSUP) return;
    int t, dst;
    if (warp < NWH) { t = 4; dst = warp; }
    else            { t = 5; dst = warp - NWH; }
    int head = lane >> 3;
    const int* rp = g_rp + 4 * (NSKU + 1) + (t == 5 ? (NWH + 1) : 0);
    const int* col = g_col + 4 * EINTRA + (t == 5 ? ECROSS : 0);
    const float* Ss = g_Ss + (size_t)t * NSKU * 4;
    const float* Sd = (t == 4) ? g_Swh : g_Ssup;
    const __half2* Hh = (const __half2*)(g_Hh + (size_t)t * NSKU * 64);
    float* Out = (t == 4) ? g_OBwh : g_OBsup;
    float sd = Sd[dst * 4 + head];
    float2 acc = make_float2(0.f, 0.f);
    float den = 0.f;
    int e = rp[dst], e1 = rp[dst + 1];
    for (; e + 1 < e1; e += 2) {
        int s0 = __ldg(&col[e]);
        int s1 = __ldg(&col[e + 1]);
        float x0 = __ldg(&Ss[s0 * 4 + head]) + sd;
        float x1 = __ldg(&Ss[s1 * 4 + head]) + sd;
        float2 h0 = __half22float2(Hh[(size_t)s0 * 32 + lane]);
        float2 h1 = __half22float2(Hh[(size_t)s1 * 32 + lane]);
        float el0 = x0 > 0.f ? x0 : (__expf(x0) - 1.f);
        float el1 = x1 > 0.f ? x1 : (__expf(x1) - 1.f);
        float w0 = __expf(el0), w1 = __expf(el1);
        acc.x += w0 * h0.x + w1 * h1.x;
        acc.y += w0 * h0.y + w1 * h1.y;
        den += w0 + w1;
    }
    if (e < e1) {
        int s0 = __ldg(&col[e]);
        float x0 = __ldg(&Ss[s0 * 4 + head]) + sd;
        float2 h0 = __half22float2(Hh[(size_t)s0 * 32 + lane]);
        float el0 = x0 > 0.f ? x0 : (__expf(x0) - 1.f);
        float w0 = __expf(el0);
        acc.x += w0 * h0.x; acc.y += w0 * h0.y; den += w0;
    }
    float inv = 1.f / (den + 1e-12f);
    *(float2*)(Out + (size_t)dst * 64 + 2 * lane) = make_float2(acc.x * inv, acc.y * inv);
}

// ------------- finish: tf32 mma GEMM [G|X] @ [PW;RW], fused LayerNorm -------------
__global__ void __launch_bounds__(256) finishT_k(
        const float* __restrict__ X, const float* __restrict__ PW,
        const float* __restrict__ RW, const float* __restrict__ pb,
        const float* __restrict__ lg, const float* __restrict__ lb,
        float* __restrict__ out, int N, int which) {
    const float* __restrict__ G = (which == 0) ? g_OA : (which == 1) ? g_OBwh : g_OBsup;
    __shared__ __align__(16) float As[128][36];
    __shared__ __align__(16) float BsT[64][36];
    int tid = threadIdx.x;
    int wid = tid >> 5, lane = tid & 31;
    int g = lane >> 2, tg = lane & 3;
    int m0 = blockIdx.x * 128;
    int mw = wid * 16;

    float acc[8][4];
    #pragma unroll
    for (int j = 0; j < 8; j++)
        #pragma unroll
        for (int c = 0; c < 4; c++) acc[j][c] = 0.f;

    for (int kb = 0; kb < 192; kb += 32) {
        #pragma unroll
        for (int q = 0; q < 4; q++) {
            int f = tid + q * 256;
            int row = f >> 3, c4 = (f & 7) * 4;
            int gr = m0 + row;
            int k = kb + c4;
            float4 v = make_float4(0.f, 0.f, 0.f, 0.f);
            if (gr < N) {
                if (k < 64) v = *(const float4*)(G + (size_t)gr * 64 + k);
                else        v = *(const float4*)(X + (size_t)gr * 128 + (k - 64));
            }
            cvt4(v);
            *(float4*)&As[row][c4] = v;
        }
        #pragma unroll
        for (int q = 0; q < 2; q++) {
            int f = tid + q * 256;
            int k = f >> 4, n4 = (f & 15) * 4;
            int gk = kb + k;
            const float* src = (gk < 64) ? (PW + (size_t)gk * 64)
                                         : (RW + (size_t)(gk - 64) * 64);
            float4 v = *(const float4*)(src + n4);
            cvt4(v);
            BsT[n4 + 0][k] = v.x; BsT[n4 + 1][k] = v.y;
            BsT[n4 + 2][k] = v.z; BsT[n4 + 3][k] = v.w;
        }
        __syncthreads();
        #pragma unroll
        for (int ks = 0; ks < 4; ks++) {
            int k0 = ks * 8 + 2 * tg;
            float2 a02 = *(const float2*)&As[mw + g][k0];
            float2 a13 = *(const float2*)&As[mw + g + 8][k0];
            u32 a0 = __float_as_uint(a02.x), a1 = __float_as_uint(a13.x);
            u32 a2 = __float_as_uint(a02.y), a3 = __float_as_uint(a13.y);
            #pragma unroll
            for (int j = 0; j < 8; j++) {
                float2 b01 = *(const float2*)&BsT[8 * j + g][k0];
                mma_tf32(acc[j], a0, a1, a2, a3,
                         __float_as_uint(b01.x), __float_as_uint(b01.y));
            }
        }
        __syncthreads();
    }

    int r0 = m0 + mw + g;
    int r1 = r0 + 8;
    float y0[8][2], y1[8][2];
    float s1a = 0.f, s2a = 0.f, s1b = 0.f, s2b = 0.f;
    #pragma unroll
    for (int j = 0; j < 8; j++) {
        float2 pbv = *(const float2*)(pb + 8 * j + 2 * tg);
        y0[j][0] = acc[j][0] + pbv.x; y0[j][1] = acc[j][1] + pbv.y;
        y1[j][0] = acc[j][2] + pbv.x; y1[j][1] = acc[j][3] + pbv.y;
        s1a += y0[j][0] + y0[j][1];
        s2a += y0[j][0] * y0[j][0] + y0[j][1] * y0[j][1];
        s1b += y1[j][0] + y1[j][1];
        s2b += y1[j][0] * y1[j][0] + y1[j][1] * y1[j][1];
    }
    #pragma unroll
    for (int o = 1; o < 4; o <<= 1) {
        s1a += __shfl_xor_sync(0xffffffffu, s1a, o);
        s2a += __shfl_xor_sync(0xffffffffu, s2a, o);
        s1b += __shfl_xor_sync(0xffffffffu, s1b, o);
        s2b += __shfl_xor_sync(0xffffffffu, s2b, o);
    }
    float mua = s1a * (1.f / 64.f);
    float vara = s2a * (1.f / 64.f) - mua * mua;
    float inva = rsqrtf(vara + 1e-5f);
    float mub = s1b * (1.f / 64.f);
    float varb = s2b * (1.f / 64.f) - mub * mub;
    float invb = rsqrtf(varb + 1e-5f);
    #pragma unroll
    for (int j = 0; j < 8; j++) {
        int c = 8 * j + 2 * tg;
        float2 gv = *(const float2*)(lg + c);
        float2 bv = *(const float2*)(lb + c);
        if (r0 < N)
            *(float2*)(out + (size_t)r0 * 64 + c) =
                make_float2((y0[j][0] - mua) * inva * gv.x + bv.x,
                            (y0[j][1] - mua) * inva * gv.y + bv.y);
        if (r1 < N)
            *(float2*)(out + (size_t)r1 * 64 + c) =
                make_float2((y1[j][0] - mub) * invb * gv.x + bv.x,
                            (y1[j][1] - mub) * invb * gv.y + bv.y);
    }
}

// ------------- launch (3-stream DAG) -------------
extern "C" void kernel_launch(void* const* d_in, const int* in_sizes, int n_in,
                              void* d_out, int out_size) {
    const float* x_sku = (const float*)d_in[0];
    const float* x_wh  = (const float*)d_in[1];
    const float* x_sup = (const float*)d_in[2];
    GP6 gp; EP6 ep;
    for (int i = 0; i < 6; i++) {
        gp.W[i] = (const float*)d_in[3 + 2 * i];
        gp.a[i] = (const float*)d_in[4 + 2 * i];
    }
    const float* proj_W = (const float*)d_in[15];
    const float* proj_b = (const float*)d_in[16];
    const float* ln_g   = (const float*)d_in[17];
    const float* ln_b   = (const float*)d_in[18];
    const float* res_W  = (const float*)d_in[19];
    for (int i = 0; i < 6; i++) ep.p[i] = (const int*)d_in[20 + i];
    float* out = (float*)d_out;

    static cudaStream_t s1 = 0, s2 = 0;
    static cudaEvent_t ev_root = 0, ev_csr = 0, ev_gemm = 0, ev_s2 = 0;
    if (!s1) {
        cudaStreamCreateWithFlags(&s1, cudaStreamNonBlocking);
        cudaStreamCreateWithFlags(&s2, cudaStreamNonBlocking);
        cudaEventCreateWithFlags(&ev_root, cudaEventDisableTiming);
        cudaEventCreateWithFlags(&ev_csr, cudaEventDisableTiming);
        cudaEventCreateWithFlags(&ev_gemm, cudaEventDisableTiming);
        cudaEventCreateWithFlags(&ev_s2, cudaEventDisableTiming);
    }

    // fork
    cudaEventRecord(ev_root, 0);
    cudaStreamWaitEvent(s1, ev_root, 0);
    cudaStreamWaitEvent(s2, ev_root, 0);

    // S1: CSR build (ticketed count -> scanA -> scanC(+blocksum) -> atomic-free fill)
    zero_deg_k<<<(TOTN + 255) / 256, 256, 0, s1>>>();
    count_k<<<dim3((EINTRA / 8 + 255) / 256, 6), 256, 0, s1>>>(ep);
    scanA_k<<<dim3(SCB, 6), 1024, 0, s1>>>();
    scanC_k<<<dim3(SCB, 6), 1024, 0, s1>>>();
    fill2_k<<<dim3((EINTRA / 8 + 255) / 256, 6), 256, 0, s1>>>(ep);
    cudaEventRecord(ev_csr, s1);

    // S2: dst-side scores (merged wh+sup)
    dstscore2_k<<<NWH + NSUP, 64, 0, s2>>>(x_wh, x_sup, gp.W[4], gp.W[5],
                                           gp.a[4], gp.a[5]);

    // S0: dense phase (tf32 tensor cores, 2 types per block, all 3 pairs)
    gemm6_k<<<dim3((NSKU + 127) / 128, 3), 256>>>(x_sku, gp);
    cudaEventRecord(ev_gemm, 0);

    // S0: sku chain
    cudaStreamWaitEvent(0, ev_csr, 0);
    agg_intra_k<<<(NSKU * 32 + 255) / 256, 256>>>();
    finishT_k<<<(NSKU + 127) / 128, 256>>>(x_sku, proj_W, res_W, proj_b, ln_g, ln_b,
                                           out, NSKU, 0);

    // S2: cross chains (merged agg)
    cudaStreamWaitEvent(s2, ev_gemm, 0);
    cudaStreamWaitEvent(s2, ev_csr, 0);
    agg_crossM_k<<<((NWH + NSUP) * 32 + 255) / 256, 256, 0, s2>>>();
    finishT_k<<<(NWH + 127) / 128, 256, 0, s2>>>(x_wh, proj_W + 64 * 64, res_W, proj_b,
                                                 ln_g, ln_b, out + (size_t)NSKU * 64, NWH, 1);
    finishT_k<<<(NSUP + 127) / 128, 256, 0, s2>>>(x_sup, proj_W + 64 * 64, res_W, proj_b,
                                                  ln_g, ln_b, out + (size_t)(NSKU + NWH) * 64,
                                                  NSUP, 2);
    cudaEventRecord(ev_s2, s2);

    // join
    cudaStreamWaitEvent(0, ev_s2, 0);
}